// round 5
// baseline (speedup 1.0000x reference)
#include <cuda_runtime.h>
#include <math.h>

#define N_S 4096
#define N_T 4096
#define R_CONST 0.05f
#define K_STRIKE 100.0f
#define S_MAX 300.0f
#define B_CONST 100.0f
#define ALPHA_STR 30.0f
#define CHI 6.0f
#define HUBER_DELTA 0.01f
#define ALPHA 2.5f

#define BLOCK_THREADS 256
#define ROWS 8
#define NTILES 2048          /* 512 row-tiles x 4 t-tiles */
#define GRID 592             /* 148 SMs x 4 CTAs: single wave */
#define TAIL_BID 591

typedef unsigned long long u64;

__device__ float    g_partials[GRID];
__device__ unsigned g_count = 0;

__device__ __forceinline__ u64 pk(float lo, float hi) {
    u64 r; asm("mov.b64 %0,{%1,%2};" : "=l"(r) : "f"(lo), "f"(hi)); return r;
}
__device__ __forceinline__ void upk(u64 v, float& lo, float& hi) {
    asm("mov.b64 {%0,%1},%2;" : "=f"(lo), "=f"(hi) : "l"(v));
}
__device__ __forceinline__ u64 f2fma(u64 a, u64 b, u64 c) {
    u64 r; asm("fma.rn.f32x2 %0,%1,%2,%3;" : "=l"(r) : "l"(a), "l"(b), "l"(c)); return r;
}
__device__ __forceinline__ u64 f2mul(u64 a, u64 b) {
    u64 r; asm("mul.rn.f32x2 %0,%1,%2;" : "=l"(r) : "l"(a), "l"(b)); return r;
}
__device__ __forceinline__ u64 f2add(u64 a, u64 b) {
    u64 r; asm("add.rn.f32x2 %0,%1,%2;" : "=l"(r) : "l"(a), "l"(b)); return r;
}

__global__ __launch_bounds__(BLOCK_THREADS, 4)
void bsloss_fused_kernel(const float* __restrict__ V, float* __restrict__ out,
                         float c1, float c2,
                         float inv2du, float invdu2, float inv2dt,
                         float pde_scale, float bc_scale, float tc_scale)
{
    const int bid  = blockIdx.x;
    const int tid  = threadIdx.x;
    const int lane = tid & 31;
    const int wrp  = tid >> 5;
    const float du = 1.0f / (float)(N_S - 1);

    __shared__ float sm_k[ROWS][5];
    __shared__ float sm_e[ROWS][16];

    float partial = 0.0f;
    u64 acc2 = 0;

    const u64 M1  = pk(-1.0f, -1.0f);
    const u64 M2  = pk(-2.0f, -2.0f);
    const u64 DT2 = pk(inv2dt, inv2dt);
    const u64 AL2 = pk(ALPHA, ALPHA);

    // ---------- persistent tile loop ----------
    for (int tile = bid; tile < NTILES; tile += GRID) {
        const int btx    = tile & 3;
        const int bty    = tile >> 2;
        const int s0     = 1 + ROWS * bty;
        const int chunkg = btx * 256 + tid;   // global float4 index 0..1023
        const int t0     = chunkg * 4;

        // prefetch first 5 rows (independent of smem barriers below)
        ulonglong2 buf[ROWS + 2];
        #pragma unroll
        for (int j = 0; j < 5; j++) {
            int s = s0 - 1 + j; s = (s > N_S - 1) ? (N_S - 1) : s;
            buf[j] = *(const ulonglong2*)(V + (size_t)s * N_T + t0);
        }

        __syncthreads();   // protect smem vs previous tile's readers
        if (tid < ROWS) {
            int s = s0 + tid;
            float u    = (float)s * du;
            float L    = c2 * u + c1 * (1.0f - u);
            float dL   = c2 - c1;
            float Sun  = (ALPHA_STR * dL * (0.5f * L * L + 1.0f)) / S_MAX;
            float Suun = (ALPHA_STR * dL * dL * L) / S_MAX;
            float Sn   = (B_CONST + ALPHA_STR * (L * L * L / CHI + L)) / S_MAX;
            float iS  = 1.0f / Sun;
            float iS2 = iS * iS;
            float iS3 = iS2 * iS;
            sm_k[tid][0] = invdu2 * iS2;
            sm_k[tid][1] = -(inv2du * Suun * iS3);
            sm_k[tid][2] = -(ALPHA * Sn * iS * inv2du);
            sm_k[tid][3] = -(Sn * Sn);
            sm_k[tid][4] = (s <= N_S - 2) ? pde_scale : 0.0f;
        }
        if (tid < ROWS * 16) {
            int re = tid >> 4, c = tid & 15;
            int colr = (c < 8) ? (c * 128 - 1) : ((c - 7) * 128);
            int g = btx * 1024 + colr;
            g = (g < 0) ? 0 : ((g > N_T - 1) ? (N_T - 1) : g);
            int se = s0 + re; se = (se > N_S - 1) ? (N_S - 1) : se;
            sm_e[re][c] = __ldg(V + (size_t)se * N_T + g);
        }
        __syncthreads();

        const u64 mask1 = (chunkg == 0)    ? 0xFFFFFFFF00000000ull : ~0ull;
        const u64 mask2 = (chunkg == 1023) ? 0x00000000FFFFFFFFull : ~0ull;

        #pragma unroll
        for (int r = 0; r < ROWS; r++) {
            // rolling prefetch: one row, 3 iterations ahead of its use
            if (r + 5 < ROWS + 2) {
                int s = s0 + 4 + r; s = (s > N_S - 1) ? (N_S - 1) : s;
                buf[r + 5] = *(const ulonglong2*)(V + (size_t)s * N_T + t0);
            }

            const float kA   = sm_k[r][0];
            const float kBn  = sm_k[r][1];
            const float kCn  = sm_k[r][2];
            const float Sn2n = sm_k[r][3];
            const float ps   = sm_k[r][4];
            const u64 kA2   = pk(kA, kA);
            const u64 kBn2  = pk(kBn, kBn);
            const u64 kCn2  = pk(kCn, kCn);
            const u64 Sn2n2 = pk(Sn2n, Sn2n);
            const u64 PS2   = pk(ps, ps);

            const u64 vm01 = buf[r].x,     vm23 = buf[r].y;
            const u64 vc01 = buf[r + 1].x, vc23 = buf[r + 1].y;
            const u64 vp01 = buf[r + 2].x, vp23 = buf[r + 2].y;

            float cx, cy, cz, cw;
            upk(vc01, cx, cy);
            upk(vc23, cz, cw);

            // cross-chunk t-neighbors: shuffles + smem-staged block-edge columns
            float lfv = __shfl_up_sync(0xFFFFFFFFu, cw, 1);
            float rtv = __shfl_down_sync(0xFFFFFFFFu, cx, 1);
            float eL = sm_e[r][wrp];
            float eR = sm_e[r][8 + wrp];
            if (lane == 0)  lfv = eL;
            if (lane == 31) rtv = eR;

            const u64 tl1 = pk(lfv, cx);
            const u64 mid = pk(cy, cz);
            const u64 tr2 = pk(cw, rtv);
            const u64 vtd1 = f2fma(tl1, M1, mid);
            const u64 vtd2 = f2fma(mid, M1, tr2);

            {   // elems 0,1
                u64 d   = f2fma(vm01, M1, vp01);
                u64 e   = f2fma(vc01, M2, f2add(vp01, vm01));
                u64 VSS = f2fma(d, kBn2, f2mul(e, kA2));
                float a, b;
                upk(VSS, a, b);
                a = fminf(100.0f, fmaxf(-100.0f, a));
                b = fminf(100.0f, fmaxf(-100.0f, b));
                u64 VSSc = pk(a, b);
                u64 res = f2fma(vc01, AL2,
                           f2fma(d, kCn2,
                            f2fma(VSSc, Sn2n2, f2mul(vtd1, DT2))));
                u64 sq = f2mul(res, res) & mask1;
                acc2 = f2fma(sq, PS2, acc2);
            }
            {   // elems 2,3
                u64 d   = f2fma(vm23, M1, vp23);
                u64 e   = f2fma(vc23, M2, f2add(vp23, vm23));
                u64 VSS = f2fma(d, kBn2, f2mul(e, kA2));
                float a, b;
                upk(VSS, a, b);
                a = fminf(100.0f, fmaxf(-100.0f, a));
                b = fminf(100.0f, fmaxf(-100.0f, b));
                u64 VSSc = pk(a, b);
                u64 res = f2fma(vc23, AL2,
                           f2fma(d, kCn2,
                            f2fma(VSSc, Sn2n2, f2mul(vtd2, DT2))));
                u64 sq = f2mul(res, res) & mask2;
                acc2 = f2fma(sq, PS2, acc2);
            }
        }
    }

    {
        float alo, ahi;
        upk(acc2, alo, ahi);
        partial = alo + ahi;
    }

    // ---------- tail work: BC row + terminal column (block 591: a 3-tile block) ----------
    if (bid == TAIL_BID) {
        float acc = 0.0f;
        const float* brow = V + (size_t)(N_S - 1) * N_T;
        const float dt_grid = 1.0f / (float)(N_T - 1);
        #pragma unroll
        for (int k = 0; k < 4; k++) {
            int t0 = (tid + 256 * k) * 4;
            float4 v4 = *(const float4*)(brow + t0);
            #pragma unroll
            for (int j = 0; j < 4; j++) {
                float v = (j == 0) ? v4.x : (j == 1) ? v4.y : (j == 2) ? v4.z : v4.w;
                float tv = (float)(t0 + j) * dt_grid;
                float target = 1.0f - K_STRIKE * __expf(-R_CONST * (1.0f - tv)) / S_MAX;
                float d = v - target;
                acc = fmaf(d * d, bc_scale, acc);
            }
        }
        #pragma unroll
        for (int k = 0; k < 16; k++) {
            int s = tid + 256 * k;
            float v = __ldg(V + (size_t)s * N_T + (N_T - 1));
            float u = (float)s * du;
            float x = 50.0f * (u - K_STRIKE / S_MAX);
            float payoff = (fmaxf(x, 0.0f) + log1pf(expf(-fabsf(x)))) / 50.0f;
            float d  = v - payoff;
            float ad = fabsf(d);
            float h  = (ad < HUBER_DELTA) ? (0.5f * d * d)
                                          : (HUBER_DELTA * (ad - 0.5f * HUBER_DELTA));
            acc = fmaf(h, tc_scale, acc);
        }
        partial += acc;
    }

    // ---------- block reduction ----------
    __shared__ float smem[BLOCK_THREADS];
    __syncthreads();
    smem[tid] = partial;
    __syncthreads();
    #pragma unroll
    for (int off = BLOCK_THREADS / 2; off >= 32; off >>= 1) {
        if (tid < off) smem[tid] += smem[tid + off];
        __syncthreads();
    }
    if (tid < 32) {
        float v = smem[tid];
        #pragma unroll
        for (int off = 16; off > 0; off >>= 1)
            v += __shfl_down_sync(0xFFFFFFFFu, v, off);
        if (tid == 0) g_partials[bid] = v;
    }

    // ---------- last-block deterministic finalize ----------
    __shared__ bool is_last;
    __threadfence();
    if (tid == 0) {
        unsigned prev = atomicAdd(&g_count, 1u);
        is_last = (prev == (unsigned)(gridDim.x - 1));
    }
    __syncthreads();
    if (is_last) {
        double a = 0.0;
        #pragma unroll
        for (int k = 0; k < 3; k++) {
            int idx = tid + k * BLOCK_THREADS;
            if (idx < GRID) a += (double)__ldcg(&g_partials[idx]);
        }
        __shared__ double dsm[BLOCK_THREADS];
        dsm[tid] = a;
        __syncthreads();
        #pragma unroll
        for (int off = BLOCK_THREADS / 2; off >= 1; off >>= 1) {
            if (tid < off) dsm[tid] += dsm[tid + off];
            __syncthreads();
        }
        if (tid == 0) {
            out[0] = (float)dsm[0];
            g_count = 0;   // reset for next graph replay
        }
    }
}

static double solve_depressed_cubic(double Q) {
    double p = 6.0;
    double q = 6.0 * Q;
    double sp = sqrt(p);
    double arg = fabs(q) / (2.0 * p * sp / (3.0 * sqrt(3.0)));
    if (arg < 1.0) arg = 1.0;
    double c = 2.0 * sp * cosh(acosh(arg) / 3.0);
    return (q >= 0.0) ? -c : c;
}

extern "C" void kernel_launch(void* const* d_in, const int* in_sizes, int n_in,
                              void* d_out, int out_size)
{
    (void)in_sizes; (void)n_in; (void)out_size;
    const float* V = (const float*)d_in[0];
    float* out = (float*)d_out;

    const double c1d = solve_depressed_cubic((100.0 - 0.0) / 30.0);
    const double c2d = solve_depressed_cubic((100.0 - 300.0) / 30.0);

    const double DU = 1.0 / (double)(N_S - 1);
    const double TAU_MAX = 0.5 * 0.2 * 0.2 * 1.0;
    const double DT_NORM = TAU_MAX / (double)(N_T - 1);

    const float inv2du = (float)(1.0 / (2.0 * DU));
    const float invdu2 = (float)(1.0 / (DU * DU));
    const float inv2dt = (float)(1.0 / (2.0 * DT_NORM));

    const float pde_scale = (float)(1.0 / ((double)(N_S - 2) * (double)(N_T - 2)));
    const float bc_scale  = (float)(10.0 / (double)N_T);
    const float tc_scale  = (float)(10.0 / (double)N_S);

    bsloss_fused_kernel<<<GRID, BLOCK_THREADS>>>(V, out, (float)c1d, (float)c2d,
                                                 inv2du, invdu2, inv2dt,
                                                 pde_scale, bc_scale, tc_scale);
}

// round 6
// speedup vs baseline: 1.4305x; 1.4305x over previous
#include <cuda_runtime.h>
#include <math.h>

#define N_S 4096
#define N_T 4096
#define R_CONST 0.05f
#define K_STRIKE 100.0f
#define S_MAX 300.0f
#define B_CONST 100.0f
#define ALPHA_STR 30.0f
#define CHI 6.0f
#define HUBER_DELTA 0.01f
#define ALPHA 2.5f

#define BLOCK_THREADS 256
#define ROWS 8
#define NP_BLOCKS (512 * 4 + 1)   /* 1 tail block + 2048 PDE tiles */

typedef unsigned long long u64;

__device__ float    g_partials[NP_BLOCKS];
__device__ unsigned g_count = 0;

__device__ __forceinline__ u64 pk(float lo, float hi) {
    u64 r; asm("mov.b64 %0,{%1,%2};" : "=l"(r) : "f"(lo), "f"(hi)); return r;
}
__device__ __forceinline__ void upk(u64 v, float& lo, float& hi) {
    asm("mov.b64 {%0,%1},%2;" : "=f"(lo), "=f"(hi) : "l"(v));
}
__device__ __forceinline__ u64 f2fma(u64 a, u64 b, u64 c) {
    u64 r; asm("fma.rn.f32x2 %0,%1,%2,%3;" : "=l"(r) : "l"(a), "l"(b), "l"(c)); return r;
}
__device__ __forceinline__ u64 f2mul(u64 a, u64 b) {
    u64 r; asm("mul.rn.f32x2 %0,%1,%2;" : "=l"(r) : "l"(a), "l"(b)); return r;
}
__device__ __forceinline__ u64 f2add(u64 a, u64 b) {
    u64 r; asm("add.rn.f32x2 %0,%1,%2;" : "=l"(r) : "l"(a), "l"(b)); return r;
}

__global__ __launch_bounds__(BLOCK_THREADS, 5)
void bsloss_fused_kernel(const float* __restrict__ V, float* __restrict__ out,
                         float c1, float c2,
                         float inv2du, float invdu2, float inv2dt,
                         float pde_scale, float bc_scale, float tc_scale)
{
    const int bid = blockIdx.x;
    const int tid = threadIdx.x;
    const float du = 1.0f / (float)(N_S - 1);

    float partial = 0.0f;

    __shared__ float sm_k[ROWS][5];

    if (bid == 0) {
        // ---------- tail block: BC row (s=4095) + terminal column (t=4095) ----------
        float acc = 0.0f;
        const float* brow = V + (size_t)(N_S - 1) * N_T;
        const float dt_grid = 1.0f / (float)(N_T - 1);
        #pragma unroll
        for (int k = 0; k < 4; k++) {
            int t0 = (tid + 256 * k) * 4;
            float4 v4 = *(const float4*)(brow + t0);
            #pragma unroll
            for (int j = 0; j < 4; j++) {
                float v = (j == 0) ? v4.x : (j == 1) ? v4.y : (j == 2) ? v4.z : v4.w;
                float tv = (float)(t0 + j) * dt_grid;
                float target = 1.0f - K_STRIKE * __expf(-R_CONST * (1.0f - tv)) / S_MAX;
                float d = v - target;
                acc = fmaf(d * d, bc_scale, acc);
            }
        }
        #pragma unroll
        for (int k = 0; k < 16; k++) {
            int s = tid + 256 * k;
            float v = __ldg(V + (size_t)s * N_T + (N_T - 1));
            float u = (float)s * du;
            float x = 50.0f * (u - K_STRIKE / S_MAX);
            float payoff = (fmaxf(x, 0.0f) + log1pf(expf(-fabsf(x)))) / 50.0f;
            float d  = v - payoff;
            float ad = fabsf(d);
            float h  = (ad < HUBER_DELTA) ? (0.5f * d * d)
                                          : (HUBER_DELTA * (ad - 0.5f * HUBER_DELTA));
            acc = fmaf(h, tc_scale, acc);
        }
        partial = acc;
    } else {
        // ---------- PDE tile: 8 rows x 1024 t-elems, processed as 2 halves of 4 rows ----------
        const int tile = bid - 1;
        const int btx  = tile & 3;
        const int bty  = tile >> 2;
        const int s0   = 1 + ROWS * bty;

        if (tid < ROWS) {
            int s = s0 + tid;
            float u    = (float)s * du;
            float L    = c2 * u + c1 * (1.0f - u);
            float dL   = c2 - c1;
            float Sun  = (ALPHA_STR * dL * (0.5f * L * L + 1.0f)) / S_MAX;
            float Suun = (ALPHA_STR * dL * dL * L) / S_MAX;
            float Sn   = (B_CONST + ALPHA_STR * (L * L * L / CHI + L)) / S_MAX;
            float iS  = 1.0f / Sun;
            float iS2 = iS * iS;
            float iS3 = iS2 * iS;
            sm_k[tid][0] = invdu2 * iS2;
            sm_k[tid][1] = -(inv2du * Suun * iS3);
            sm_k[tid][2] = -(ALPHA * Sn * iS * inv2du);
            sm_k[tid][3] = -(Sn * Sn);
            sm_k[tid][4] = (s <= N_S - 2) ? pde_scale : 0.0f;
        }
        __syncthreads();

        const int chunk = btx * 256 + tid;   // 0..1023
        const int t0    = chunk * 4;
        const int lane  = tid & 31;

        const u64 M1  = pk(-1.0f, -1.0f);
        const u64 M2  = pk(-2.0f, -2.0f);
        const u64 DT2 = pk(inv2dt, inv2dt);
        const u64 AL2 = pk(ALPHA, ALPHA);
        const u64 mask1 = (chunk == 0)    ? 0xFFFFFFFF00000000ull : ~0ull;
        const u64 mask2 = (chunk == 1023) ? 0x00000000FFFFFFFFull : ~0ull;

        u64 acc2 = 0;

        #pragma unroll
        for (int h = 0; h < 2; h++) {
            const int b0 = s0 + 4 * h;

            // front-batched loads for this half: 6 row vectors (MLP=6)
            ulonglong2 buf[6];
            #pragma unroll
            for (int j = 0; j < 6; j++) {
                int srow = b0 - 1 + j;
                srow = (srow > N_S - 1) ? (N_S - 1) : srow;
                buf[j] = *(const ulonglong2*)(V + (size_t)srow * N_T + t0);
            }

            // boundary-lane t-neighbors (predicated; interior lanes use shuffles)
            float edgeL[4], edgeR[4];
            #pragma unroll
            for (int j = 0; j < 4; j++) { edgeL[j] = 0.0f; edgeR[j] = 0.0f; }
            if (lane == 0 && chunk != 0) {
                #pragma unroll
                for (int j = 0; j < 4; j++) {
                    int srow = b0 + j; srow = (srow > N_S - 1) ? (N_S - 1) : srow;
                    edgeL[j] = __ldg(V + (size_t)srow * N_T + t0 - 1);
                }
            }
            if (lane == 31 && chunk != 1023) {
                #pragma unroll
                for (int j = 0; j < 4; j++) {
                    int srow = b0 + j; srow = (srow > N_S - 1) ? (N_S - 1) : srow;
                    edgeR[j] = __ldg(V + (size_t)srow * N_T + t0 + 4);
                }
            }

            #pragma unroll
            for (int r = 0; r < 4; r++) {
                const int kr = 4 * h + r;
                const float kA   = sm_k[kr][0];
                const float kBn  = sm_k[kr][1];
                const float kCn  = sm_k[kr][2];
                const float Sn2n = sm_k[kr][3];
                const float ps   = sm_k[kr][4];
                const u64 kA2   = pk(kA, kA);
                const u64 kBn2  = pk(kBn, kBn);
                const u64 kCn2  = pk(kCn, kCn);
                const u64 Sn2n2 = pk(Sn2n, Sn2n);
                const u64 PS2   = pk(ps, ps);

                const u64 vm01 = buf[r].x,     vm23 = buf[r].y;
                const u64 vc01 = buf[r + 1].x, vc23 = buf[r + 1].y;
                const u64 vp01 = buf[r + 2].x, vp23 = buf[r + 2].y;

                float cx, cy, cz, cw;
                upk(vc01, cx, cy);
                upk(vc23, cz, cw);

                float lfv = __shfl_up_sync(0xFFFFFFFFu, cw, 1);
                float rtv = __shfl_down_sync(0xFFFFFFFFu, cx, 1);
                if (lane == 0)  lfv = edgeL[r];
                if (lane == 31) rtv = edgeR[r];

                const u64 tl1 = pk(lfv, cx);
                const u64 mid = pk(cy, cz);
                const u64 tr2 = pk(cw, rtv);
                const u64 vtd1 = f2fma(tl1, M1, mid);
                const u64 vtd2 = f2fma(mid, M1, tr2);

                {   // elems 0,1
                    u64 d   = f2fma(vm01, M1, vp01);
                    u64 e   = f2fma(vc01, M2, f2add(vp01, vm01));
                    u64 VSS = f2fma(d, kBn2, f2mul(e, kA2));
                    float a, b;
                    upk(VSS, a, b);
                    a = fminf(100.0f, fmaxf(-100.0f, a));
                    b = fminf(100.0f, fmaxf(-100.0f, b));
                    u64 VSSc = pk(a, b);
                    u64 res = f2fma(vc01, AL2,
                               f2fma(d, kCn2,
                                f2fma(VSSc, Sn2n2, f2mul(vtd1, DT2))));
                    u64 sq = f2mul(res, res) & mask1;
                    acc2 = f2fma(sq, PS2, acc2);
                }
                {   // elems 2,3
                    u64 d   = f2fma(vm23, M1, vp23);
                    u64 e   = f2fma(vc23, M2, f2add(vp23, vm23));
                    u64 VSS = f2fma(d, kBn2, f2mul(e, kA2));
                    float a, b;
                    upk(VSS, a, b);
                    a = fminf(100.0f, fmaxf(-100.0f, a));
                    b = fminf(100.0f, fmaxf(-100.0f, b));
                    u64 VSSc = pk(a, b);
                    u64 res = f2fma(vc23, AL2,
                               f2fma(d, kCn2,
                                f2fma(VSSc, Sn2n2, f2mul(vtd2, DT2))));
                    u64 sq = f2mul(res, res) & mask2;
                    acc2 = f2fma(sq, PS2, acc2);
                }
            }
        }
        float alo, ahi;
        upk(acc2, alo, ahi);
        partial = alo + ahi;
    }

    // ---------- block reduction ----------
    __shared__ float smem[BLOCK_THREADS];
    smem[tid] = partial;
    __syncthreads();
    #pragma unroll
    for (int off = BLOCK_THREADS / 2; off >= 32; off >>= 1) {
        if (tid < off) smem[tid] += smem[tid + off];
        __syncthreads();
    }
    if (tid < 32) {
        float v = smem[tid];
        #pragma unroll
        for (int off = 16; off > 0; off >>= 1)
            v += __shfl_down_sync(0xFFFFFFFFu, v, off);
        if (tid == 0) g_partials[bid] = v;
    }

    // ---------- last-block deterministic finalize ----------
    __shared__ bool is_last;
    __threadfence();
    if (tid == 0) {
        unsigned prev = atomicAdd(&g_count, 1u);
        is_last = (prev == (unsigned)(gridDim.x - 1));
    }
    __syncthreads();
    if (is_last) {
        double a = 0.0;
        #pragma unroll
        for (int k = 0; k < 9; k++) {
            int idx = tid + k * BLOCK_THREADS;
            if (idx < NP_BLOCKS) a += (double)__ldcg(&g_partials[idx]);
        }
        __shared__ double dsm[BLOCK_THREADS];
        dsm[tid] = a;
        __syncthreads();
        #pragma unroll
        for (int off = BLOCK_THREADS / 2; off >= 1; off >>= 1) {
            if (tid < off) dsm[tid] += dsm[tid + off];
            __syncthreads();
        }
        if (tid == 0) {
            out[0] = (float)dsm[0];
            g_count = 0;   // reset for next graph replay
        }
    }
}

static double solve_depressed_cubic(double Q) {
    double p = 6.0;
    double q = 6.0 * Q;
    double sp = sqrt(p);
    double arg = fabs(q) / (2.0 * p * sp / (3.0 * sqrt(3.0)));
    if (arg < 1.0) arg = 1.0;
    double c = 2.0 * sp * cosh(acosh(arg) / 3.0);
    return (q >= 0.0) ? -c : c;
}

extern "C" void kernel_launch(void* const* d_in, const int* in_sizes, int n_in,
                              void* d_out, int out_size)
{
    (void)in_sizes; (void)n_in; (void)out_size;
    const float* V = (const float*)d_in[0];
    float* out = (float*)d_out;

    const double c1d = solve_depressed_cubic((100.0 - 0.0) / 30.0);
    const double c2d = solve_depressed_cubic((100.0 - 300.0) / 30.0);

    const double DU = 1.0 / (double)(N_S - 1);
    const double TAU_MAX = 0.5 * 0.2 * 0.2 * 1.0;
    const double DT_NORM = TAU_MAX / (double)(N_T - 1);

    const float inv2du = (float)(1.0 / (2.0 * DU));
    const float invdu2 = (float)(1.0 / (DU * DU));
    const float inv2dt = (float)(1.0 / (2.0 * DT_NORM));

    const float pde_scale = (float)(1.0 / ((double)(N_S - 2) * (double)(N_T - 2)));
    const float bc_scale  = (float)(10.0 / (double)N_T);
    const float tc_scale  = (float)(10.0 / (double)N_S);

    bsloss_fused_kernel<<<NP_BLOCKS, BLOCK_THREADS>>>(V, out, (float)c1d, (float)c2d,
                                                      inv2du, invdu2, inv2dt,
                                                      pde_scale, bc_scale, tc_scale);
}

// round 8
// speedup vs baseline: 1.4465x; 1.0111x over previous
#include <cuda_runtime.h>
#include <math.h>

#define N_S 4096
#define N_T 4096
#define R_CONST 0.05f
#define K_STRIKE 100.0f
#define S_MAX 300.0f
#define B_CONST 100.0f
#define ALPHA_STR 30.0f
#define CHI 6.0f
#define HUBER_DELTA 0.01f
#define ALPHA 2.5f

#define BLOCK_THREADS 256
#define ROWS 8
#define NP_BLOCKS (512 * 4 + 1)   /* 1 tail block + 2048 PDE tiles */

typedef unsigned long long u64;

__device__ float    g_partials[NP_BLOCKS];
__device__ unsigned g_count = 0;

__device__ __forceinline__ u64 pk(float lo, float hi) {
    u64 r; asm("mov.b64 %0,{%1,%2};" : "=l"(r) : "f"(lo), "f"(hi)); return r;
}
__device__ __forceinline__ void upk(u64 v, float& lo, float& hi) {
    asm("mov.b64 {%0,%1},%2;" : "=f"(lo), "=f"(hi) : "l"(v));
}
__device__ __forceinline__ u64 f2fma(u64 a, u64 b, u64 c) {
    u64 r; asm("fma.rn.f32x2 %0,%1,%2,%3;" : "=l"(r) : "l"(a), "l"(b), "l"(c)); return r;
}
__device__ __forceinline__ u64 f2mul(u64 a, u64 b) {
    u64 r; asm("mul.rn.f32x2 %0,%1,%2;" : "=l"(r) : "l"(a), "l"(b)); return r;
}
__device__ __forceinline__ u64 f2add(u64 a, u64 b) {
    u64 r; asm("add.rn.f32x2 %0,%1,%2;" : "=l"(r) : "l"(a), "l"(b)); return r;
}
// gpu-scope acq_rel atomic add: release-orders prior STGs (at L2) without the
// membar.gpu -> CCTL.IVALL L1D flush that __threadfence() would emit.
__device__ __forceinline__ unsigned atom_add_acqrel(unsigned* p, unsigned v) {
    unsigned old;
    asm volatile("atom.add.acq_rel.gpu.u32 %0,[%1],%2;"
                 : "=r"(old) : "l"(p), "r"(v) : "memory");
    return old;
}

__global__ __launch_bounds__(BLOCK_THREADS, 5)
void bsloss_fused_kernel(const float* __restrict__ V, float* __restrict__ out,
                         float c1, float c2,
                         float inv2du, float invdu2, float inv2dt,
                         float pde_scale, float bc_scale, float tc_scale)
{
    const int bid = blockIdx.x;
    const int tid = threadIdx.x;
    const float du = 1.0f / (float)(N_S - 1);

    float partial = 0.0f;

    __shared__ u64 sm_k2[ROWS][5];   // per-row constants, pre-duplicated (lo==hi)

    if (bid == 0) {
        // ---------- tail block: BC row (s=4095) + terminal column (t=4095) ----------
        float acc = 0.0f;
        const float* brow = V + (size_t)(N_S - 1) * N_T;
        const float dt_grid = 1.0f / (float)(N_T - 1);
        #pragma unroll
        for (int k = 0; k < 4; k++) {
            int t0 = (tid + 256 * k) * 4;
            float4 v4 = *(const float4*)(brow + t0);
            #pragma unroll
            for (int j = 0; j < 4; j++) {
                float v = (j == 0) ? v4.x : (j == 1) ? v4.y : (j == 2) ? v4.z : v4.w;
                float tv = (float)(t0 + j) * dt_grid;
                float target = 1.0f - K_STRIKE * __expf(-R_CONST * (1.0f - tv)) / S_MAX;
                float d = v - target;
                acc = fmaf(d * d, bc_scale, acc);
            }
        }
        #pragma unroll
        for (int k = 0; k < 16; k++) {
            int s = tid + 256 * k;
            float v = __ldg(V + (size_t)s * N_T + (N_T - 1));
            float u = (float)s * du;
            float x = 50.0f * (u - K_STRIKE / S_MAX);
            float payoff = (fmaxf(x, 0.0f) + log1pf(expf(-fabsf(x)))) / 50.0f;
            float d  = v - payoff;
            float ad = fabsf(d);
            float h  = (ad < HUBER_DELTA) ? (0.5f * d * d)
                                          : (HUBER_DELTA * (ad - 0.5f * HUBER_DELTA));
            acc = fmaf(h, tc_scale, acc);
        }
        partial = acc;
    } else {
        // ---------- PDE tile: 8 rows x 1024 t-elems, processed as 2 halves of 4 rows ----------
        const int tile = bid - 1;
        const int btx  = tile & 3;
        const int bty  = tile >> 2;
        const int s0   = 1 + ROWS * bty;

        if (tid < ROWS) {
            int s = s0 + tid;
            float u    = (float)s * du;
            float L    = c2 * u + c1 * (1.0f - u);
            float dL   = c2 - c1;
            float Sun  = (ALPHA_STR * dL * (0.5f * L * L + 1.0f)) / S_MAX;
            float Suun = (ALPHA_STR * dL * dL * L) / S_MAX;
            float Sn   = (B_CONST + ALPHA_STR * (L * L * L / CHI + L)) / S_MAX;
            float iS  = 1.0f / Sun;
            float iS2 = iS * iS;
            float iS3 = iS2 * iS;
            float kA   = invdu2 * iS2;
            float kBn  = -(inv2du * Suun * iS3);
            float kCn  = -(ALPHA * Sn * iS * inv2du);
            float Sn2n = -(Sn * Sn);
            float ps   = (s <= N_S - 2) ? pde_scale : 0.0f;
            sm_k2[tid][0] = pk(kA, kA);
            sm_k2[tid][1] = pk(kBn, kBn);
            sm_k2[tid][2] = pk(kCn, kCn);
            sm_k2[tid][3] = pk(Sn2n, Sn2n);
            sm_k2[tid][4] = pk(ps, ps);
        }
        __syncthreads();

        const int chunk = btx * 256 + tid;   // 0..1023
        const int t0    = chunk * 4;
        const int lane  = tid & 31;

        const u64 M1  = pk(-1.0f, -1.0f);
        const u64 M2  = pk(-2.0f, -2.0f);
        const u64 DT2 = pk(inv2dt, inv2dt);
        const u64 AL2 = pk(ALPHA, ALPHA);
        const u64 mask1 = (chunk == 0)    ? 0xFFFFFFFF00000000ull : ~0ull;
        const u64 mask2 = (chunk == 1023) ? 0x00000000FFFFFFFFull : ~0ull;

        u64 acc2 = 0;

        #pragma unroll
        for (int h = 0; h < 2; h++) {
            const int b0 = s0 + 4 * h;

            // front-batched loads for this half: 6 row vectors (MLP=6)
            ulonglong2 buf[6];
            #pragma unroll
            for (int j = 0; j < 6; j++) {
                int srow = b0 - 1 + j;
                srow = (srow > N_S - 1) ? (N_S - 1) : srow;
                buf[j] = *(const ulonglong2*)(V + (size_t)srow * N_T + t0);
            }

            // boundary-lane t-neighbors (predicated; interior lanes use shuffles)
            float edgeL[4], edgeR[4];
            #pragma unroll
            for (int j = 0; j < 4; j++) { edgeL[j] = 0.0f; edgeR[j] = 0.0f; }
            if (lane == 0 && chunk != 0) {
                #pragma unroll
                for (int j = 0; j < 4; j++) {
                    int srow = b0 + j; srow = (srow > N_S - 1) ? (N_S - 1) : srow;
                    edgeL[j] = __ldg(V + (size_t)srow * N_T + t0 - 1);
                }
            }
            if (lane == 31 && chunk != 1023) {
                #pragma unroll
                for (int j = 0; j < 4; j++) {
                    int srow = b0 + j; srow = (srow > N_S - 1) ? (N_S - 1) : srow;
                    edgeR[j] = __ldg(V + (size_t)srow * N_T + t0 + 4);
                }
            }

            #pragma unroll
            for (int r = 0; r < 4; r++) {
                const int kr = 4 * h + r;
                const u64 kA2   = sm_k2[kr][0];
                const u64 kBn2  = sm_k2[kr][1];
                const u64 kCn2  = sm_k2[kr][2];
                const u64 Sn2n2 = sm_k2[kr][3];
                const u64 PS2   = sm_k2[kr][4];

                const u64 vm01 = buf[r].x,     vm23 = buf[r].y;
                const u64 vc01 = buf[r + 1].x, vc23 = buf[r + 1].y;
                const u64 vp01 = buf[r + 2].x, vp23 = buf[r + 2].y;

                float cx, cy, cz, cw;
                upk(vc01, cx, cy);
                upk(vc23, cz, cw);

                float lfv = __shfl_up_sync(0xFFFFFFFFu, cw, 1);
                float rtv = __shfl_down_sync(0xFFFFFFFFu, cx, 1);
                if (lane == 0)  lfv = edgeL[r];
                if (lane == 31) rtv = edgeR[r];

                const u64 tl1 = pk(lfv, cx);
                const u64 mid = pk(cy, cz);
                const u64 tr2 = pk(cw, rtv);
                const u64 vtd1 = f2fma(tl1, M1, mid);
                const u64 vtd2 = f2fma(mid, M1, tr2);

                {   // elems 0,1
                    u64 d   = f2fma(vm01, M1, vp01);
                    u64 e   = f2fma(vc01, M2, f2add(vp01, vm01));
                    u64 VSS = f2fma(d, kBn2, f2mul(e, kA2));
                    float a, b;
                    upk(VSS, a, b);
                    a = fminf(100.0f, fmaxf(-100.0f, a));
                    b = fminf(100.0f, fmaxf(-100.0f, b));
                    u64 VSSc = pk(a, b);
                    u64 res = f2fma(vc01, AL2,
                               f2fma(d, kCn2,
                                f2fma(VSSc, Sn2n2, f2mul(vtd1, DT2))));
                    u64 sq = f2mul(res, res) & mask1;
                    acc2 = f2fma(sq, PS2, acc2);
                }
                {   // elems 2,3
                    u64 d   = f2fma(vm23, M1, vp23);
                    u64 e   = f2fma(vc23, M2, f2add(vp23, vm23));
                    u64 VSS = f2fma(d, kBn2, f2mul(e, kA2));
                    float a, b;
                    upk(VSS, a, b);
                    a = fminf(100.0f, fmaxf(-100.0f, a));
                    b = fminf(100.0f, fmaxf(-100.0f, b));
                    u64 VSSc = pk(a, b);
                    u64 res = f2fma(vc23, AL2,
                               f2fma(d, kCn2,
                                f2fma(VSSc, Sn2n2, f2mul(vtd2, DT2))));
                    u64 sq = f2mul(res, res) & mask2;
                    acc2 = f2fma(sq, PS2, acc2);
                }
            }
        }
        float alo, ahi;
        upk(acc2, alo, ahi);
        partial = alo + ahi;
    }

    // ---------- block reduction ----------
    __shared__ float smem[BLOCK_THREADS];
    smem[tid] = partial;
    __syncthreads();
    #pragma unroll
    for (int off = BLOCK_THREADS / 2; off >= 32; off >>= 1) {
        if (tid < off) smem[tid] += smem[tid + off];
        __syncthreads();
    }
    if (tid < 32) {
        float v = smem[tid];
        #pragma unroll
        for (int off = 16; off > 0; off >>= 1)
            v += __shfl_down_sync(0xFFFFFFFFu, v, off);
        if (tid == 0) g_partials[bid] = v;
    }

    // ---------- last-block deterministic finalize (no __threadfence / L1 flush) ----------
    __shared__ bool is_last;
    __syncthreads();
    if (tid == 0) {
        unsigned prev = atom_add_acqrel(&g_count, 1u);
        is_last = (prev == (unsigned)(gridDim.x - 1));
    }
    __syncthreads();
    if (is_last) {
        double a = 0.0;
        #pragma unroll
        for (int k = 0; k < 9; k++) {
            int idx = tid + k * BLOCK_THREADS;
            if (idx < NP_BLOCKS) a += (double)__ldcg(&g_partials[idx]);
        }
        __shared__ double dsm[BLOCK_THREADS];
        dsm[tid] = a;
        __syncthreads();
        #pragma unroll
        for (int off = BLOCK_THREADS / 2; off >= 1; off >>= 1) {
            if (tid < off) dsm[tid] += dsm[tid + off];
            __syncthreads();
        }
        if (tid == 0) {
            out[0] = (float)dsm[0];
            g_count = 0;   // reset for next graph replay
        }
    }
}

static double solve_depressed_cubic(double Q) {
    double p = 6.0;
    double q = 6.0 * Q;
    double sp = sqrt(p);
    double arg = fabs(q) / (2.0 * p * sp / (3.0 * sqrt(3.0)));
    if (arg < 1.0) arg = 1.0;
    double c = 2.0 * sp * cosh(acosh(arg) / 3.0);
    return (q >= 0.0) ? -c : c;
}

extern "C" void kernel_launch(void* const* d_in, const int* in_sizes, int n_in,
                              void* d_out, int out_size)
{
    (void)in_sizes; (void)n_in; (void)out_size;
    const float* V = (const float*)d_in[0];
    float* out = (float*)d_out;

    const double c1d = solve_depressed_cubic((100.0 - 0.0) / 30.0);
    const double c2d = solve_depressed_cubic((100.0 - 300.0) / 30.0);

    const double DU = 1.0 / (double)(N_S - 1);
    const double TAU_MAX = 0.5 * 0.2 * 0.2 * 1.0;
    const double DT_NORM = TAU_MAX / (double)(N_T - 1);

    const float inv2du = (float)(1.0 / (2.0 * DU));
    const float invdu2 = (float)(1.0 / (DU * DU));
    const float inv2dt = (float)(1.0 / (2.0 * DT_NORM));

    const float pde_scale = (float)(1.0 / ((double)(N_S - 2) * (double)(N_T - 2)));
    const float bc_scale  = (float)(10.0 / (double)N_T);
    const float tc_scale  = (float)(10.0 / (double)N_S);

    bsloss_fused_kernel<<<NP_BLOCKS, BLOCK_THREADS>>>(V, out, (float)c1d, (float)c2d,
                                                      inv2du, invdu2, inv2dt,
                                                      pde_scale, bc_scale, tc_scale);
}